// round 8
// baseline (speedup 1.0000x reference)
#include <cuda_runtime.h>
#include <math.h>

#define ZDIM    4736      // 4*UNITS
#define LN10K   9.210340371976184f
#define NBLK    128
#define NTHR    512

// Device globals (no allocation allowed)
__device__ __align__(16) float g_KC[64 * 2 * 64];   // [l-1][h*64+k], l = 1..64
__device__ __align__(16) float g_VC[64 * 2 * 64];
__device__ __align__(16) float g_o[128 * 64];       // o row-major: [b][k]
__device__ unsigned g_bar1 = 0, g_bar2 = 0, g_done = 0;

__device__ __forceinline__ float sigd(float x) { return 1.0f / (1.0f + __expf(-x)); }

__device__ __forceinline__ float pe_val(int l, int i) {
    float e = (float)(2 * (i / 2)) * (1.0f / 64.0f);
    float invfreq = __expf(-e * LN10K);
    float ang = (float)l * invfreq;
    return (i & 1) ? cosf(ang) : sinf(ang);
}

// Packed dual-FMA: d = a*b + d on two f32 lanes (sm_100+).
__device__ __forceinline__ void fma2(unsigned long long& d,
                                     unsigned long long a, unsigned long long b) {
    asm("fma.rn.f32x2 %0, %1, %2, %0;" : "+l"(d) : "l"(a), "l"(b));
}
__device__ __forceinline__ float pairsum(unsigned long long v) {
    return __uint_as_float((unsigned)v) + __uint_as_float((unsigned)(v >> 32));
}

// Grid-wide barrier: all 128 blocks co-resident; tight spin.
__device__ __forceinline__ void grid_bar(unsigned* ctr) {
    __syncthreads();
    if (threadIdx.x == 0) {
        __threadfence();
        atomicAdd(ctr, 1u);
        volatile unsigned* v = (volatile unsigned*)ctr;
        while (*v < (unsigned)NBLK) { }
        __threadfence();
    }
    __syncthreads();
}

// Overlayed scratch (keeps static smem under 48KB)
struct SmemA { float4 cs4[512]; float pq[512]; float pk[512]; float pv[512]; };
struct SmemB { float VCs[64 * 128]; float scratch[512]; };
struct SmemC { float Hs[8][132]; };
union  SmemU { SmemA a; SmemB b; SmemC c; };

// ---------------------------------------------------------------------------
// Single fused kernel. grid = 128 (block = batch row b; also produces half a
// KC/VC row: l = bid/2 + 1, K if bid even else V). block = 512.
// ---------------------------------------------------------------------------
__global__ void __launch_bounds__(NTHR) k_fused(
        const float* __restrict__ queries, const float* __restrict__ values,
        const float* __restrict__ Wi, const float* __restrict__ bi,
        const float* __restrict__ Wm, const float* __restrict__ bm,
        const float* __restrict__ Wq, const float* __restrict__ bq,
        const float* __restrict__ Wk, const float* __restrict__ bk,
        const float* __restrict__ Wv, const float* __restrict__ bv,
        const float* __restrict__ Wo, const float* __restrict__ bo,
        const float* __restrict__ Wx, const float* __restrict__ bl,
        float* __restrict__ out, float m) {
    const int bid = blockIdx.x;
    const int t = threadIdx.x;

    __shared__ __align__(16) SmemU u;
    __shared__ __align__(16) float Wg[8][3][64];
    __shared__ float Bv[8][3];
    __shared__ float aug0[64];
    __shared__ float augl[64];
    __shared__ float q[128], k0[128], v0[128];
    __shared__ float attn[130];
    __shared__ float ctx[128];

    const int j0 = bid * 8;
    const int grpoff[3] = {0, 2368, 3552};         // zi, zg, zo column groups
    const int lrow = (bid >> 1) + 1;

    // ---- A0: prefetch phase-C Wx tile (latency hidden behind A/B)
    #pragma unroll
    for (int r = 0; r < 3; r++) {
        int idx = r * NTHR + t;                    // 1536 elements
        int jj = idx & 7;
        int kg = idx >> 3;
        int g  = kg % 3;
        int k  = kg / 3;
        Wg[jj][g][k] = Wx[k * ZDIM + grpoff[g] + j0 + jj];
    }
    if (t < 24) Bv[t & 7][t >> 3] = bl[grpoff[t >> 3] + j0 + (t & 7)];

    // ---- colsum(Wm): 8 independent float4 loads per thread
    {
        const float4* wm4 = (const float4*)Wm;     // 4096 float4
        float4 acc = make_float4(0.f, 0.f, 0.f, 0.f);
        #pragma unroll
        for (int r = 0; r < 8; r++) {
            float4 v = wm4[r * NTHR + t];
            acc.x += v.x; acc.y += v.y; acc.z += v.z; acc.w += v.w;
        }
        u.a.cs4[t] = acc;
    }

    // ---- A2: emb_in + PE[0] (t<64), x read directly from global (uniform)
    if (t < 64) {
        float s = bi[t];
        #pragma unroll
        for (int i = 0; i < 16; i++) s += queries[bid * 16 + i] * Wi[i * 64 + t];
        #pragma unroll
        for (int i = 0; i < 16; i++)
            s += values[(bid / 16) * 128 + 112 + i] * Wi[(16 + i) * 64 + t];
        aug0[t] = s + ((t & 1) ? 1.0f : 0.0f);
    }
    __syncthreads();   // aug0 + cs4 ready

    // ---- A3: q/k0/v0 matvec 4-way d-split; spare range computes augl
    {
        int col = t & 127, qtr = t >> 7;
        float aq = 0.f, ak = 0.f, av = 0.f;
        #pragma unroll
        for (int d = qtr * 16; d < qtr * 16 + 16; d++) {
            float a = aug0[d];
            aq += a * Wq[d * 128 + col];
            ak += a * Wk[d * 128 + col];
            av += a * Wv[d * 128 + col];
        }
        u.a.pq[t] = aq; u.a.pk[t] = ak; u.a.pv[t] = av;
    }
    if (t >= 448) {    // augl for d = t-448 (cs4 ready since sync1)
        int d = t - 448;
        const float* csf = (const float*)u.a.cs4;
        float cs = 0.f;
        #pragma unroll
        for (int r = 0; r < 32; r++) cs += csf[(d >> 2) * 4 + (d & 3) + 64 * r];
        augl[d] = m * cs + bm[d] + pe_val(lrow, d);
    }
    __syncthreads();   // partials + augl ready

    // combine q/k0/v0 (t<128); then all threads do A4 partials
    if (t < 128) {
        q[t]  = bq[t] + u.a.pq[t] + u.a.pq[t + 128] + u.a.pq[t + 256] + u.a.pq[t + 384];
        k0[t] = bk[t] + u.a.pk[t] + u.a.pk[t + 128] + u.a.pk[t + 256] + u.a.pk[t + 384];
        v0[t] = bv[t] + u.a.pv[t] + u.a.pv[t + 128] + u.a.pv[t + 256] + u.a.pv[t + 384];
    }
    // ---- A4: half a KC/VC row, 4-way d-split
    {
        const float* W = (bid & 1) ? Wv : Wk;
        int col = t & 127, qtr = t >> 7;
        float a = 0.f;
        #pragma unroll
        for (int d = qtr * 16; d < qtr * 16 + 16; d++)
            a += augl[d] * W[d * 128 + col];
        u.a.pk[t] = a;     // pk reused (q/k/v combine already read it? NO - combine above reads pk!)
    }
    __syncthreads();
    if (t < 128) {
        const float* bb = (bid & 1) ? bv : bk;
        float* dst      = (bid & 1) ? g_VC : g_KC;
        dst[(lrow - 1) * 128 + t] =
            bb[t] + u.a.pk[t] + u.a.pk[t + 128] + u.a.pk[t + 256] + u.a.pk[t + 384];
    }

    grid_bar(&g_bar1);   // KC/VC published

    // ---- B1: logits 2-way d-split (t<260) | VC prefetch to shared (t>=260)
    if (t < 260) {
        int pair = t >> 1, dh = t & 1;
        int h = (pair >= 65) ? 1 : 0;
        int l = pair - h * 65;
        const float* kp = (l == 0) ? &k0[h * 64] : &g_KC[(l - 1) * 128 + h * 64];
        float s = 0.0f;
        #pragma unroll
        for (int d = dh * 32; d < dh * 32 + 32; d++) s += q[h * 64 + d] * kp[d];
        u.b.scratch[t] = s;
    } else {
        const float4* src = (const float4*)g_VC;
        float4* dst = (float4*)u.b.VCs;
        int base = t - 260;                        // 252 loader threads
        #pragma unroll
        for (int r = 0; r < 9; r++) {
            int idx = base + 252 * r;
            if (idx < 2048) dst[idx] = src[idx];
        }
    }
    __syncthreads();

    // ---- B2: softmax with folded pair-combine (warp 0 -> h0, warp 1 -> h1)
    {
        int w = t >> 5, lane = t & 31;
        if (w < 2) {
            int base = w * 65;
            float a0 = (u.b.scratch[2 * (base + lane)] + u.b.scratch[2 * (base + lane) + 1]) * 0.125f;
            float a1 = (u.b.scratch[2 * (base + 32 + lane)] + u.b.scratch[2 * (base + 32 + lane) + 1]) * 0.125f;
            float a2 = (lane == 0)
                ? (u.b.scratch[2 * (base + 64)] + u.b.scratch[2 * (base + 64) + 1]) * 0.125f
                : -1e30f;
            float mx = fmaxf(fmaxf(a0, a1), a2);
            #pragma unroll
            for (int off = 16; off > 0; off >>= 1)
                mx = fmaxf(mx, __shfl_xor_sync(0xffffffffu, mx, off));
            float e0 = __expf(a0 - mx);
            float e1 = __expf(a1 - mx);
            float e2 = (lane == 0) ? __expf(a2 - mx) : 0.0f;
            float sum = e0 + e1 + e2;
            #pragma unroll
            for (int off = 16; off > 0; off >>= 1)
                sum += __shfl_xor_sync(0xffffffffu, sum, off);
            float inv = 1.0f / sum;
            attn[base + lane] = e0 * inv;
            attn[base + 32 + lane] = e1 * inv;
            if (lane == 0) attn[base + 64] = e2 * inv;
        }
    }
    __syncthreads();

    // ---- B3: ctx 4-way l-split from shared VCs
    {
        int col = t & 127, lq = t >> 7;
        int h = col >> 6;
        float s = (lq == 0) ? attn[h * 65] * v0[col] : 0.0f;
        #pragma unroll
        for (int r = lq * 16; r < lq * 16 + 16; r++)
            s += attn[h * 65 + r + 1] * u.b.VCs[r * 128 + col];
        u.b.scratch[t] = s;
    }
    __syncthreads();
    if (t < 128)
        ctx[t] = u.b.scratch[t] + u.b.scratch[t + 128] + u.b.scratch[t + 256] + u.b.scratch[t + 384];
    __syncthreads();

    // ---- B4: o matvec 8-way hk-split
    {
        int col = t & 63, oct = t >> 6;
        float s = 0.f;
        const float* Wp = Wo + (oct * 16) * 64 + col;
        #pragma unroll
        for (int hk = 0; hk < 16; hk++)
            s += ctx[oct * 16 + hk] * Wp[hk * 64];
        u.b.scratch[t] = s;
    }
    __syncthreads();
    if (t < 64) {
        float s = bo[t];
        #pragma unroll
        for (int r = 0; r < 8; r++) s += u.b.scratch[t + 64 * r];
        g_o[bid * 64 + t] = s;
    }

    grid_bar(&g_bar2);   // o published

    // ---- C: gate GEMM, thread = (b, jsel); jsel covers 2 of 8 j-columns
    {
        int b = t & 127, jsel = t >> 7;
        ulonglong2 o2[16];
        const ulonglong2* gp = (const ulonglong2*)(g_o + b * 64);
        #pragma unroll
        for (int i = 0; i < 16; i++) o2[i] = gp[i];

        #pragma unroll
        for (int jr = 0; jr < 2; jr++) {
            int jj = jsel * 2 + jr;
            unsigned long long zi2 = 0ull, zg2 = 0ull, zo2 = 0ull;
            const ulonglong2* wi2 = (const ulonglong2*)Wg[jj][0];
            const ulonglong2* wg2 = (const ulonglong2*)Wg[jj][1];
            const ulonglong2* wo2 = (const ulonglong2*)Wg[jj][2];
            #pragma unroll
            for (int k = 0; k < 16; k++) {
                ulonglong2 wa = wi2[k], wb = wg2[k], wc = wo2[k];
                ulonglong2 ov = o2[k];
                fma2(zi2, ov.x, wa.x); fma2(zi2, ov.y, wa.y);
                fma2(zg2, ov.x, wb.x); fma2(zg2, ov.y, wb.y);
                fma2(zo2, ov.x, wc.x); fma2(zo2, ov.y, wc.y);
            }
            float zi = pairsum(zi2) + Bv[jj][0];
            float zg = pairsum(zg2) + Bv[jj][1];
            float zo = pairsum(zo2) + Bv[jj][2];
            float c = sigd(zi) * tanhf(zg);
            u.c.Hs[jj][b] = sigd(zo) * tanhf(c);
        }
    }
    __syncthreads();

    // staged coalesced writes
    #pragma unroll
    for (int r = 0; r < 2; r++) {
        int idx = r * NTHR + t;
        int jj = idx & 7, bb = idx >> 3;
        out[bb * 1024 + j0 + jj] = u.c.Hs[jj][bb];
    }

    // ---- Cleanup: last block resets barrier counters for the next replay
    __syncthreads();
    if (t == 0) {
        __threadfence();
        unsigned d = atomicAdd(&g_done, 1u);
        if (d == (unsigned)(NBLK - 1)) {
            g_bar1 = 0; g_bar2 = 0;
            __threadfence();
            g_done = 0;
        }
    }
}

// ---------------------------------------------------------------------------
// Host-side replica of the pot decay (input-independent).
static float sig_h(float x) { return 1.0f / (1.0f + expf(-x)); }
static float decay_h(float pc, float po) {
    float t0 = 0.07915332f * sig_h(100.0f * (0.0f - 0.5f)) * (1.5931877f - pc);
    float t1 = 1.0334609f  * sig_h(100.0f * (pc - 0.07879465f)) * (1.4378392f - pc);
    float t2 = 1.3365093f  * sig_h(100.0f * (po - 0.06618887f)) * (0.0f - pc);
    float t3 = 0.4505964f  * (0.0f - pc);
    return t0 + t1 + t2 + t3;
}
static float pot_scalar_h() {
    float p0 = 0.0f, p1 = 1.0f;
    const float PART = (float)(1.5573331 / 2.0);
    for (int s = 0; s < 7; s++)
        for (int d = 0; d < 2; d++) {
            float n0 = decay_h(p0, p1);
            float n1 = decay_h(p1, p0);
            p0 += n0 * PART;
            p1 += n1 * PART;
        }
    return p0;
}

extern "C" void kernel_launch(void* const* d_in, const int* in_sizes, int n_in,
                              void* d_out, int out_size) {
    const float* queries = (const float*)d_in[0];
    const float* values  = (const float*)d_in[1];
    const float* Wi      = (const float*)d_in[2];
    const float* bi      = (const float*)d_in[3];
    const float* Wm      = (const float*)d_in[4];
    const float* bm      = (const float*)d_in[5];
    const float* Wq      = (const float*)d_in[6];
    const float* bq      = (const float*)d_in[7];
    const float* Wk      = (const float*)d_in[8];
    const float* bk      = (const float*)d_in[9];
    const float* Wv      = (const float*)d_in[10];
    const float* bv      = (const float*)d_in[11];
    const float* Wo      = (const float*)d_in[12];
    const float* bo      = (const float*)d_in[13];
    const float* Wx      = (const float*)d_in[14];
    const float* bl      = (const float*)d_in[15];
    float* out = (float*)d_out;

    float m = pot_scalar_h();

    k_fused<<<NBLK, NTHR>>>(queries, values, Wi, bi, Wm, bm, Wq, bq, Wk, bk,
                            Wv, bv, Wo, bo, Wx, bl, out, m);
}